// round 2
// baseline (speedup 1.0000x reference)
#include <cuda_runtime.h>

#define TT 8192
#define EE 1024
#define DD 1028
#define NTAG 50
#define L2E 1.4426950408889634f

// Scratch (no cudaMalloc allowed): pre-activations [T+1][16] (pad row for prefetch), h outputs [T][4]
__device__ float g_pre[(TT + 1) * 16];
__device__ float g_h[TT * 4];

__device__ __forceinline__ float ex2f(float x) {
    float y; asm("ex2.approx.f32 %0, %1;" : "=f"(y) : "f"(x)); return y;
}
__device__ __forceinline__ float rcpf(float x) {
    float y; asm("rcp.approx.f32 %0, %1;" : "=f"(y) : "f"(x)); return y;
}

// ---------------------------------------------------------------------------
// Phase 1: pre[t][g*4+w] = emb[sentence[t]] . W_g[w, :1024]  + b_g[w] + th_g[w]
// One warp handles 4 rows (amortizes weight loads). Grid: 2048 warps.
// ---------------------------------------------------------------------------
__global__ __launch_bounds__(256) void pre_kernel(
    const int* __restrict__ sentence, const float* __restrict__ emb,
    const float* __restrict__ Wf, const float* __restrict__ bf,
    const float* __restrict__ Wi, const float* __restrict__ bi,
    const float* __restrict__ Wu, const float* __restrict__ bu,
    const float* __restrict__ Wo, const float* __restrict__ bo,
    const float* __restrict__ thf, const float* __restrict__ thi,
    const float* __restrict__ thu, const float* __restrict__ tho)
{
    int gwarp = (blockIdx.x * blockDim.x + threadIdx.x) >> 5;  // 0..2047
    int lane = threadIdx.x & 31;
    int t0 = gwarp * 4;

    const float4* e4[4];
#pragma unroll
    for (int r = 0; r < 4; r++)
        e4[r] = (const float4*)(emb + (size_t)sentence[t0 + r] * EE);

    const float* Wp[4] = {Wf, Wi, Wu, Wo};

    float acc[4][16];
#pragma unroll
    for (int r = 0; r < 4; r++)
#pragma unroll
        for (int k = 0; k < 16; k++) acc[r][k] = 0.0f;

    // 1024 floats = 256 float4 per row; lane strides by 32.
    for (int j = lane; j < 256; j += 32) {
        float4 ev[4];
#pragma unroll
        for (int r = 0; r < 4; r++) ev[r] = e4[r][j];
#pragma unroll
        for (int k = 0; k < 16; k++) {
            // W row base offset (k&3)*1028 floats = 4112 bytes, 16B-aligned -> float4 OK
            float4 wv = ((const float4*)(Wp[k >> 2] + (k & 3) * DD))[j];
#pragma unroll
            for (int r = 0; r < 4; r++) {
                acc[r][k] = fmaf(ev[r].x, wv.x, acc[r][k]);
                acc[r][k] = fmaf(ev[r].y, wv.y, acc[r][k]);
                acc[r][k] = fmaf(ev[r].z, wv.z, acc[r][k]);
                acc[r][k] = fmaf(ev[r].w, wv.w, acc[r][k]);
            }
        }
    }

    // Warp butterfly reduce each accumulator
#pragma unroll
    for (int r = 0; r < 4; r++)
#pragma unroll
        for (int k = 0; k < 16; k++) {
#pragma unroll
            for (int off = 16; off > 0; off >>= 1)
                acc[r][k] += __shfl_xor_sync(0xffffffffu, acc[r][k], off);
        }

    if (lane == 0) {
        const float* bp[4] = {bf, bi, bu, bo};
        const float* tp[4] = {thf, thi, thu, tho};
#pragma unroll
        for (int r = 0; r < 4; r++) {
#pragma unroll
            for (int k = 0; k < 16; k++) {
                g_pre[(t0 + r) * 16 + k] =
                    acc[r][k] + bp[k >> 2][k & 3] + tp[k >> 2][k & 3];
            }
        }
    }
}

// ---------------------------------------------------------------------------
// Phase 2: sequential LSTM scan, single warp.
// lane = g*4 + w (mirrored in lanes 16..31). Each lane computes its gate's
// 4 cosines redundantly (products stay local), 1 activation, then shuffles.
//
// qlayer simplification (CNOT ring on a product state):
//   out0 = c1*c2*c3, out1 = c0*c1, out2 = c0*c1*c2, out3 = c0*c1*c2*c3
// with c_w = cos(pre_w + Wh_g[w,:] . h)   (theta/bias folded into pre).
// ---------------------------------------------------------------------------
__global__ __launch_bounds__(32) void scan_kernel(
    const float* __restrict__ Wf, const float* __restrict__ Wi,
    const float* __restrict__ Wu, const float* __restrict__ Wo)
{
    const unsigned FULL = 0xffffffffu;
    int lane = threadIdx.x & 31;
    int w = lane & 3;
    int g = (lane >> 2) & 3;

    const float* Wg = (g == 0) ? Wf : (g == 1) ? Wi : (g == 2) ? Wu : Wo;

    // Recurrent 4x4 block of this lane's gate: wh[j*4+k] multiplies h_k into z_j
    float wh[16];
#pragma unroll
    for (int jj = 0; jj < 16; jj++)
        wh[jj] = Wg[(jj >> 2) * DD + EE + (jj & 3)];

    // Activation: act(x) = A * rcp(1 + ex2(B*x)) + C
    //   sigmoid: A=1, B=-log2(e), C=0 ; tanh (gate u, g==2): A=2, B=-2log2(e), C=-1
    float A = (g == 2) ? 2.0f : 1.0f;
    float B = (g == 2) ? (-2.0f * L2E) : (-L2E);
    float C = (g == 2) ? -1.0f : 0.0f;

    float h0 = 0.f, h1 = 0.f, h2 = 0.f, h3 = 0.f;
    float cst = 0.f;  // c-state for wire w (replicated across gate groups)

    const float4* preg = (const float4*)g_pre;  // [T+1][4 gates] of float4(w0..w3)
    float4 pv = preg[g];  // t = 0

    for (int t = 0; t < TT; t++) {
        float4 pn = preg[(t + 1) * 4 + g];  // prefetch next step (pad row at t=T-1)

        float z0 = fmaf(wh[3],  h3, fmaf(wh[2],  h2, fmaf(wh[1],  h1, fmaf(wh[0],  h0, pv.x))));
        float z1 = fmaf(wh[7],  h3, fmaf(wh[6],  h2, fmaf(wh[5],  h1, fmaf(wh[4],  h0, pv.y))));
        float z2 = fmaf(wh[11], h3, fmaf(wh[10], h2, fmaf(wh[9],  h1, fmaf(wh[8],  h0, pv.z))));
        float z3 = fmaf(wh[15], h3, fmaf(wh[14], h2, fmaf(wh[13], h1, fmaf(wh[12], h0, pv.w))));

        float c0 = __cosf(z0);
        float c1 = __cosf(z1);
        float c2 = __cosf(z2);
        float c3 = __cosf(z3);

        float c12  = c1 * c2;
        float c123 = c12 * c3;
        float q0 = c123;        // wire0: c1 c2 c3
        float q1 = c0 * c1;     // wire1
        float q2 = c0 * c12;    // wire2
        float q3 = c0 * c123;   // wire3

        float x = (w == 0) ? q0 : (w == 1) ? q1 : (w == 2) ? q2 : q3;
        float act = fmaf(A, rcpf(1.0f + ex2f(B * x)), C);

        // Gather this wire's f, i, u, o from gate lanes
        float fw = __shfl_sync(FULL, act,      w);
        float iw = __shfl_sync(FULL, act,  4 + w);
        float uw = __shfl_sync(FULL, act,  8 + w);
        float ow = __shfl_sync(FULL, act, 12 + w);

        cst = fmaf(fw, cst, iw * uw);
        float th = fmaf(2.0f, rcpf(1.0f + ex2f(-2.0f * L2E * cst)), -1.0f);
        float hn = ow * th;

        if (lane < 4) g_h[t * 4 + lane] = hn;

        h0 = __shfl_sync(FULL, hn, 0);
        h1 = __shfl_sync(FULL, hn, 1);
        h2 = __shfl_sync(FULL, hn, 2);
        h3 = __shfl_sync(FULL, hn, 3);

        pv = pn;
    }
}

// ---------------------------------------------------------------------------
// Phase 3: tag logits + log_softmax. One warp per timestep.
// ---------------------------------------------------------------------------
__global__ __launch_bounds__(128) void tag_kernel(
    const float* __restrict__ Wt, const float* __restrict__ bt,
    float* __restrict__ out)
{
    int gw = (blockIdx.x * blockDim.x + threadIdx.x) >> 5;
    int lane = threadIdx.x & 31;
    if (gw >= TT) return;

    float4 h = *(const float4*)(g_h + gw * 4);

    float l0 = -1e30f, l1 = -1e30f;
    if (lane < NTAG) {
        const float* wr = Wt + lane * 4;
        l0 = bt[lane] + h.x * wr[0] + h.y * wr[1] + h.z * wr[2] + h.w * wr[3];
    }
    int tag2 = lane + 32;
    if (tag2 < NTAG) {
        const float* wr = Wt + tag2 * 4;
        l1 = bt[tag2] + h.x * wr[0] + h.y * wr[1] + h.z * wr[2] + h.w * wr[3];
    }

    float m = fmaxf(l0, l1);
#pragma unroll
    for (int off = 16; off > 0; off >>= 1)
        m = fmaxf(m, __shfl_xor_sync(0xffffffffu, m, off));

    float s = 0.0f;
    if (lane < NTAG) s += expf(l0 - m);
    if (tag2 < NTAG) s += expf(l1 - m);
#pragma unroll
    for (int off = 16; off > 0; off >>= 1)
        s += __shfl_xor_sync(0xffffffffu, s, off);

    float lz = m + logf(s);
    if (lane < NTAG) out[gw * NTAG + lane] = l0 - lz;
    if (tag2 < NTAG) out[gw * NTAG + tag2] = l1 - lz;
}

// ---------------------------------------------------------------------------
extern "C" void kernel_launch(void* const* d_in, const int* in_sizes, int n_in,
                              void* d_out, int out_size)
{
    const int*   sentence  = (const int*)d_in[0];
    const float* embedding = (const float*)d_in[1];
    const float* Wf  = (const float*)d_in[2];
    const float* bf  = (const float*)d_in[3];
    const float* Wi  = (const float*)d_in[4];
    const float* bi  = (const float*)d_in[5];
    const float* Wu  = (const float*)d_in[6];
    const float* bu  = (const float*)d_in[7];
    const float* Wo  = (const float*)d_in[8];
    const float* bo  = (const float*)d_in[9];
    const float* thf = (const float*)d_in[10];
    const float* thi = (const float*)d_in[11];
    const float* thu = (const float*)d_in[12];
    const float* tho = (const float*)d_in[13];
    const float* Wt  = (const float*)d_in[14];
    const float* bt  = (const float*)d_in[15];
    float* out = (float*)d_out;

    // Phase 1: 2048 warps, 8 warps/block -> 256 blocks
    pre_kernel<<<256, 256>>>(sentence, embedding, Wf, bf, Wi, bi, Wu, bu,
                             Wo, bo, thf, thi, thu, tho);
    // Phase 2: single-warp sequential scan
    scan_kernel<<<1, 32>>>(Wf, Wi, Wu, Wo);
    // Phase 3: one warp per timestep, 4 warps/block -> 2048 blocks
    tag_kernel<<<TT / 4, 128>>>(Wt, bt, out);
}

// round 3
// speedup vs baseline: 38.2899x; 38.2899x over previous
#include <cuda_runtime.h>

#define TT 8192
#define EE 1024
#define DD 1028
#define NTAG 50
#define L2E 1.4426950408889634f

#define CHUNK 64
#define NCHUNK (TT / CHUNK)   // 128

// Scratch (no cudaMalloc allowed)
__device__ float g_pre[(TT + 1) * 16];      // pre-activations, +1 pad row for prefetch
__device__ float g_h[TT * 4];               // h outputs
__device__ float g_bnd[2][NCHUNK][8];       // chunk-boundary states: h0..3, c0..3

__device__ __forceinline__ float ex2f(float x) {
    float y; asm("ex2.approx.f32 %0, %1;" : "=f"(y) : "f"(x)); return y;
}
__device__ __forceinline__ float rcpf(float x) {
    float y; asm("rcp.approx.f32 %0, %1;" : "=f"(y) : "f"(x)); return y;
}

// ---------------------------------------------------------------------------
// Phase 1: pre[t][g*4+w] = emb[sentence[t]] . W_g[w, :1024] + b_g[w] + th_g[w]
// One warp handles 4 timesteps. 2048 warps.
// ---------------------------------------------------------------------------
__global__ __launch_bounds__(256) void pre_kernel(
    const int* __restrict__ sentence, const float* __restrict__ emb,
    const float* __restrict__ Wf, const float* __restrict__ bf,
    const float* __restrict__ Wi, const float* __restrict__ bi,
    const float* __restrict__ Wu, const float* __restrict__ bu,
    const float* __restrict__ Wo, const float* __restrict__ bo,
    const float* __restrict__ thf, const float* __restrict__ thi,
    const float* __restrict__ thu, const float* __restrict__ tho)
{
    int gwarp = (blockIdx.x * blockDim.x + threadIdx.x) >> 5;  // 0..2047
    int lane = threadIdx.x & 31;
    int t0 = gwarp * 4;

    const float4* e4[4];
#pragma unroll
    for (int r = 0; r < 4; r++)
        e4[r] = (const float4*)(emb + (size_t)sentence[t0 + r] * EE);

    const float* Wp[4] = {Wf, Wi, Wu, Wo};

    float acc[4][16];
#pragma unroll
    for (int r = 0; r < 4; r++)
#pragma unroll
        for (int k = 0; k < 16; k++) acc[r][k] = 0.0f;

    for (int j = lane; j < 256; j += 32) {
        float4 ev[4];
#pragma unroll
        for (int r = 0; r < 4; r++) ev[r] = e4[r][j];
#pragma unroll
        for (int k = 0; k < 16; k++) {
            float4 wv = ((const float4*)(Wp[k >> 2] + (k & 3) * DD))[j];
#pragma unroll
            for (int r = 0; r < 4; r++) {
                acc[r][k] = fmaf(ev[r].x, wv.x, acc[r][k]);
                acc[r][k] = fmaf(ev[r].y, wv.y, acc[r][k]);
                acc[r][k] = fmaf(ev[r].z, wv.z, acc[r][k]);
                acc[r][k] = fmaf(ev[r].w, wv.w, acc[r][k]);
            }
        }
    }

#pragma unroll
    for (int r = 0; r < 4; r++)
#pragma unroll
        for (int k = 0; k < 16; k++) {
#pragma unroll
            for (int off = 16; off > 0; off >>= 1)
                acc[r][k] += __shfl_xor_sync(0xffffffffu, acc[r][k], off);
        }

    if (lane == 0) {
        const float* bp[4] = {bf, bi, bu, bo};
        const float* tp[4] = {thf, thi, thu, tho};
#pragma unroll
        for (int r = 0; r < 4; r++)
#pragma unroll
            for (int k = 0; k < 16; k++)
                g_pre[(t0 + r) * 16 + k] =
                    acc[r][k] + bp[k >> 2][k & 3] + tp[k >> 2][k & 3];
    }
}

// ---------------------------------------------------------------------------
// Phase 2: chunk-parallel LSTM scan with boundary refinement.
//
// The state map is a contraction: q = prod(cos) in [-1,1] => f <= sigmoid(1)
// = 0.731, one-step Jacobian norm rho <~ 0.85. Chunk j (64 steps) started
// from an approximate state converges to the true trajectory at rate rho^s.
// Pass 0: all chunks from zero state. Pass k: chunk j restarts from pass
// k-1's end-state of chunk j-1. After 3 passes boundary error ~ rho^128 < 1e-6.
//
// Per-warp layout: lane = g*4 + w (mirrored x2). qlayer collapses to parity
// cosine products: out0=c1c2c3, out1=c0c1, out2=c0c1c2, out3=c0c1c2c3.
// Chunk's pre-activations staged in smem to keep L2 latency off the chain.
// ---------------------------------------------------------------------------
__global__ __launch_bounds__(32) void scan_pass(
    const float* __restrict__ Wf, const float* __restrict__ Wi,
    const float* __restrict__ Wu, const float* __restrict__ Wo,
    int pass)
{
    __shared__ float4 s_pre[(CHUNK + 1) * 4];   // [t_local][gate] = wires w0..w3

    const unsigned FULL = 0xffffffffu;
    int j = blockIdx.x;            // chunk index
    int lane = threadIdx.x & 31;
    int w = lane & 3;
    int g = (lane >> 2) & 3;

    // Stage this chunk's pre rows (+1 prefetch row) into smem.
    // Chunk rows are contiguous: float4 base = j*CHUNK*4.
    const float4* gp4 = (const float4*)g_pre;
    for (int k = lane; k < (CHUNK + 1) * 4; k += 32)
        s_pre[k] = gp4[j * (CHUNK * 4) + k];

    const float* Wg = (g == 0) ? Wf : (g == 1) ? Wi : (g == 2) ? Wu : Wo;
    float wh[16];
#pragma unroll
    for (int jj = 0; jj < 16; jj++)
        wh[jj] = Wg[(jj >> 2) * DD + EE + (jj & 3)];

    float A = (g == 2) ? 2.0f : 1.0f;
    float B = (g == 2) ? (-2.0f * L2E) : (-L2E);
    float C = (g == 2) ? -1.0f : 0.0f;

    // Initial state: zeros on pass 0 or chunk 0; else previous pass's
    // end-state of chunk j-1 (ping-pong buffers: pass1 reads buf0, pass2 buf1).
    float h0 = 0.f, h1 = 0.f, h2 = 0.f, h3 = 0.f, cst = 0.f;
    if (pass > 0 && j > 0) {
        const float* b = g_bnd[pass - 1 == 0 ? 0 : (pass - 1) & 1][j - 1];
        // pass=1 -> read g_bnd[0]; pass=2 -> read g_bnd[1]
        h0 = b[0]; h1 = b[1]; h2 = b[2]; h3 = b[3];
        cst = b[4 + w];
    }

    __syncthreads();

    float4 pv = s_pre[g];
    float hn = 0.0f;
    int tg = j * CHUNK;

    for (int tl = 0; tl < CHUNK; tl++) {
        float4 pn = s_pre[(tl + 1) * 4 + g];

        float z0 = fmaf(wh[3],  h3, fmaf(wh[2],  h2, fmaf(wh[1],  h1, fmaf(wh[0],  h0, pv.x))));
        float z1 = fmaf(wh[7],  h3, fmaf(wh[6],  h2, fmaf(wh[5],  h1, fmaf(wh[4],  h0, pv.y))));
        float z2 = fmaf(wh[11], h3, fmaf(wh[10], h2, fmaf(wh[9],  h1, fmaf(wh[8],  h0, pv.z))));
        float z3 = fmaf(wh[15], h3, fmaf(wh[14], h2, fmaf(wh[13], h1, fmaf(wh[12], h0, pv.w))));

        float c0 = __cosf(z0);
        float c1 = __cosf(z1);
        float c2 = __cosf(z2);
        float c3 = __cosf(z3);

        float c12  = c1 * c2;
        float c123 = c12 * c3;
        float q0 = c123;
        float q1 = c0 * c1;
        float q2 = c0 * c12;
        float q3 = c0 * c123;

        float x = (w == 0) ? q0 : (w == 1) ? q1 : (w == 2) ? q2 : q3;
        float act = fmaf(A, rcpf(1.0f + ex2f(B * x)), C);

        float fw = __shfl_sync(FULL, act,      w);
        float iw = __shfl_sync(FULL, act,  4 + w);
        float uw = __shfl_sync(FULL, act,  8 + w);
        float ow = __shfl_sync(FULL, act, 12 + w);

        cst = fmaf(fw, cst, iw * uw);
        float th = fmaf(2.0f, rcpf(1.0f + ex2f(-2.0f * L2E * cst)), -1.0f);
        hn = ow * th;

        if (lane < 4) g_h[(tg + tl) * 4 + lane] = hn;

        h0 = __shfl_sync(FULL, hn, 0);
        h1 = __shfl_sync(FULL, hn, 1);
        h2 = __shfl_sync(FULL, hn, 2);
        h3 = __shfl_sync(FULL, hn, 3);

        pv = pn;
    }

    // Write chunk-end boundary state: pass0 -> buf0, pass1 -> buf1.
    // (pass2 needs no write; skip to avoid useless traffic)
    if (pass < 2 && lane < 4) {
        g_bnd[pass & 1][j][lane]     = hn;   // hn on lane<4 is wire `lane`'s h
        g_bnd[pass & 1][j][4 + lane] = cst;  // cst on lane<4 is wire `lane`'s c
    }
}

// ---------------------------------------------------------------------------
// Phase 3: tag logits + log_softmax. One warp per timestep.
// ---------------------------------------------------------------------------
__global__ __launch_bounds__(128) void tag_kernel(
    const float* __restrict__ Wt, const float* __restrict__ bt,
    float* __restrict__ out)
{
    int gw = (blockIdx.x * blockDim.x + threadIdx.x) >> 5;
    int lane = threadIdx.x & 31;
    if (gw >= TT) return;

    float4 h = *(const float4*)(g_h + gw * 4);

    float l0 = -1e30f, l1 = -1e30f;
    if (lane < NTAG) {
        const float* wr = Wt + lane * 4;
        l0 = bt[lane] + h.x * wr[0] + h.y * wr[1] + h.z * wr[2] + h.w * wr[3];
    }
    int tag2 = lane + 32;
    if (tag2 < NTAG) {
        const float* wr = Wt + tag2 * 4;
        l1 = bt[tag2] + h.x * wr[0] + h.y * wr[1] + h.z * wr[2] + h.w * wr[3];
    }

    float m = fmaxf(l0, l1);
#pragma unroll
    for (int off = 16; off > 0; off >>= 1)
        m = fmaxf(m, __shfl_xor_sync(0xffffffffu, m, off));

    float s = 0.0f;
    if (lane < NTAG) s += expf(l0 - m);
    if (tag2 < NTAG) s += expf(l1 - m);
#pragma unroll
    for (int off = 16; off > 0; off >>= 1)
        s += __shfl_xor_sync(0xffffffffu, s, off);

    float lz = m + logf(s);
    if (lane < NTAG) out[gw * NTAG + lane] = l0 - lz;
    if (tag2 < NTAG) out[gw * NTAG + tag2] = l1 - lz;
}

// ---------------------------------------------------------------------------
extern "C" void kernel_launch(void* const* d_in, const int* in_sizes, int n_in,
                              void* d_out, int out_size)
{
    const int*   sentence  = (const int*)d_in[0];
    const float* embedding = (const float*)d_in[1];
    const float* Wf  = (const float*)d_in[2];
    const float* bf  = (const float*)d_in[3];
    const float* Wi  = (const float*)d_in[4];
    const float* bi  = (const float*)d_in[5];
    const float* Wu  = (const float*)d_in[6];
    const float* bu  = (const float*)d_in[7];
    const float* Wo  = (const float*)d_in[8];
    const float* bo  = (const float*)d_in[9];
    const float* thf = (const float*)d_in[10];
    const float* thi = (const float*)d_in[11];
    const float* thu = (const float*)d_in[12];
    const float* tho = (const float*)d_in[13];
    const float* Wt  = (const float*)d_in[14];
    const float* bt  = (const float*)d_in[15];
    float* out = (float*)d_out;

    pre_kernel<<<256, 256>>>(sentence, embedding, Wf, bf, Wi, bi, Wu, bu,
                             Wo, bo, thf, thi, thu, tho);

    // Chunk-parallel scan: 3 refinement passes, 128 chunks x 64 steps.
    scan_pass<<<NCHUNK, 32>>>(Wf, Wi, Wu, Wo, 0);
    scan_pass<<<NCHUNK, 32>>>(Wf, Wi, Wu, Wo, 1);
    scan_pass<<<NCHUNK, 32>>>(Wf, Wi, Wu, Wo, 2);

    tag_kernel<<<TT / 4, 128>>>(Wt, bt, out);
}

// round 4
// speedup vs baseline: 50.1730x; 1.3103x over previous
#include <cuda_runtime.h>

#define TT 8192
#define EE 1024
#define DD 1028
#define NTAG 50

#define CHUNK 32
#define NCHUNK (TT / CHUNK)   // 256
#define NPASS 4

// Scratch (no cudaMalloc allowed)
__device__ float g_pre[(TT + 1) * 16];      // pre-activations, +1 pad row for prefetch
__device__ float g_h[TT * 4];               // h outputs
__device__ float g_bnd[2][NCHUNK][8];       // chunk-boundary states: h0..3, c0..3

__device__ __forceinline__ float tanhf_fast(float x) {
    float y; asm("tanh.approx.f32 %0, %1;" : "=f"(y) : "f"(x)); return y;
}

// ---------------------------------------------------------------------------
// Phase 1: pre[t][g*4+w] = emb[sentence[t]] . W_g[w, :1024] + b_g[w] + th_g[w]
// One warp handles 2 timesteps (regs down, warps up -> more MLP). 4096 warps.
// ---------------------------------------------------------------------------
__global__ __launch_bounds__(256) void pre_kernel(
    const int* __restrict__ sentence, const float* __restrict__ emb,
    const float* __restrict__ Wf, const float* __restrict__ bf,
    const float* __restrict__ Wi, const float* __restrict__ bi,
    const float* __restrict__ Wu, const float* __restrict__ bu,
    const float* __restrict__ Wo, const float* __restrict__ bo,
    const float* __restrict__ thf, const float* __restrict__ thi,
    const float* __restrict__ thu, const float* __restrict__ tho)
{
    int gwarp = (blockIdx.x * blockDim.x + threadIdx.x) >> 5;  // 0..4095
    int lane = threadIdx.x & 31;
    int t0 = gwarp * 2;

    const float4* e4[2];
#pragma unroll
    for (int r = 0; r < 2; r++)
        e4[r] = (const float4*)(emb + (size_t)sentence[t0 + r] * EE);

    const float* Wp[4] = {Wf, Wi, Wu, Wo};

    float acc[2][16];
#pragma unroll
    for (int r = 0; r < 2; r++)
#pragma unroll
        for (int k = 0; k < 16; k++) acc[r][k] = 0.0f;

    for (int j = lane; j < 256; j += 32) {
        float4 ev[2];
#pragma unroll
        for (int r = 0; r < 2; r++) ev[r] = e4[r][j];
#pragma unroll
        for (int k = 0; k < 16; k++) {
            float4 wv = ((const float4*)(Wp[k >> 2] + (k & 3) * DD))[j];
#pragma unroll
            for (int r = 0; r < 2; r++) {
                acc[r][k] = fmaf(ev[r].x, wv.x, acc[r][k]);
                acc[r][k] = fmaf(ev[r].y, wv.y, acc[r][k]);
                acc[r][k] = fmaf(ev[r].z, wv.z, acc[r][k]);
                acc[r][k] = fmaf(ev[r].w, wv.w, acc[r][k]);
            }
        }
    }

#pragma unroll
    for (int r = 0; r < 2; r++)
#pragma unroll
        for (int k = 0; k < 16; k++) {
#pragma unroll
            for (int off = 16; off > 0; off >>= 1)
                acc[r][k] += __shfl_xor_sync(0xffffffffu, acc[r][k], off);
        }

    if (lane == 0) {
        const float* bp[4] = {bf, bi, bu, bo};
        const float* tp[4] = {thf, thi, thu, tho};
#pragma unroll
        for (int r = 0; r < 2; r++)
#pragma unroll
            for (int k = 0; k < 16; k++)
                g_pre[(t0 + r) * 16 + k] =
                    acc[r][k] + bp[k >> 2][k & 3] + tp[k >> 2][k & 3];
    }
}

// ---------------------------------------------------------------------------
// Phase 2: chunk-parallel LSTM scan with boundary refinement.
//
// Contraction: gate input q = prod(cos) in [-1,1] => f <= sigmoid(1)=0.731,
// one-step Jacobian norm rho <~ 0.85-0.9. Pass 0: all 256 chunks (32 steps)
// from zero state. Pass k: chunk j restarts from pass k-1's end state of
// chunk j-1. After 4 passes the boundary error ~ rho^96 < 1e-4 worst case.
//
// lane = g*4+w (mirrored x2). qlayer collapses to parity cosine products:
// out0=c1c2c3, out1=c0c1, out2=c0c1c2, out3=c0c1c2c3.
// Activations via HW tanh: sigmoid(x) = 0.5*tanh(x/2)+0.5.
// ---------------------------------------------------------------------------
template<bool LAST>
__global__ __launch_bounds__(32) void scan_pass(
    const float* __restrict__ Wf, const float* __restrict__ Wi,
    const float* __restrict__ Wu, const float* __restrict__ Wo,
    int pass)
{
    __shared__ float4 s_pre[(CHUNK + 1) * 4];   // [t_local][gate] = wires w0..w3

    const unsigned FULL = 0xffffffffu;
    int j = blockIdx.x;            // chunk index
    int lane = threadIdx.x & 31;
    int w = lane & 3;
    int g = (lane >> 2) & 3;

    // Stage this chunk's pre rows (+1 prefetch row) into smem.
    const float4* gp4 = (const float4*)g_pre;
    for (int k = lane; k < (CHUNK + 1) * 4; k += 32)
        s_pre[k] = gp4[j * (CHUNK * 4) + k];

    const float* Wg = (g == 0) ? Wf : (g == 1) ? Wi : (g == 2) ? Wu : Wo;
    float wh[16];
#pragma unroll
    for (int jj = 0; jj < 16; jj++)
        wh[jj] = Wg[(jj >> 2) * DD + EE + (jj & 3)];

    // act = A2 * tanh(B2 * x) + C2 : sigmoid A2=C2=0.5,B2=0.5 ; tanh-gate A2=B2=1,C2=0
    float A2 = (g == 2) ? 1.0f : 0.5f;
    float B2 = (g == 2) ? 1.0f : 0.5f;
    float C2 = (g == 2) ? 0.0f : 0.5f;

    float h0 = 0.f, h1 = 0.f, h2 = 0.f, h3 = 0.f, cst = 0.f;
    if (pass > 0 && j > 0) {
        const float* b = g_bnd[(pass - 1) & 1][j - 1];
        h0 = b[0]; h1 = b[1]; h2 = b[2]; h3 = b[3];
        cst = b[4 + w];
    }

    __syncthreads();

    float4 pv = s_pre[g];
    float hn = 0.0f;
    int tg = j * CHUNK;

    for (int tl = 0; tl < CHUNK; tl++) {
        float4 pn = s_pre[(tl + 1) * 4 + g];

        // Tree-form z: depth 3 instead of 4
        float z0 = fmaf(wh[1],  h1, fmaf(wh[0],  h0, pv.x)) + fmaf(wh[3],  h3, wh[2]  * h2);
        float z1 = fmaf(wh[5],  h1, fmaf(wh[4],  h0, pv.y)) + fmaf(wh[7],  h3, wh[6]  * h2);
        float z2 = fmaf(wh[9],  h1, fmaf(wh[8],  h0, pv.z)) + fmaf(wh[11], h3, wh[10] * h2);
        float z3 = fmaf(wh[13], h1, fmaf(wh[12], h0, pv.w)) + fmaf(wh[15], h3, wh[14] * h2);

        float c0 = __cosf(z0);
        float c1 = __cosf(z1);
        float c2 = __cosf(z2);
        float c3 = __cosf(z3);

        float c12  = c1 * c2;
        float c123 = c12 * c3;
        float q0 = c123;
        float q1 = c0 * c1;
        float q2 = c0 * c12;
        float q3 = c0 * c123;

        float x = (w == 0) ? q0 : (w == 1) ? q1 : (w == 2) ? q2 : q3;
        float act = fmaf(A2, tanhf_fast(B2 * x), C2);

        float fw = __shfl_sync(FULL, act,      w);
        float iw = __shfl_sync(FULL, act,  4 + w);
        float uw = __shfl_sync(FULL, act,  8 + w);
        float ow = __shfl_sync(FULL, act, 12 + w);

        cst = fmaf(fw, cst, iw * uw);
        hn = ow * tanhf_fast(cst);

        if (LAST) {
            if (lane < 4) g_h[(tg + tl) * 4 + lane] = hn;
        }

        h0 = __shfl_sync(FULL, hn, 0);
        h1 = __shfl_sync(FULL, hn, 1);
        h2 = __shfl_sync(FULL, hn, 2);
        h3 = __shfl_sync(FULL, hn, 3);

        pv = pn;
    }

    if (!LAST && lane < 4) {
        g_bnd[pass & 1][j][lane]     = hn;   // wire `lane`'s h
        g_bnd[pass & 1][j][4 + lane] = cst;  // wire `lane`'s c
    }
}

// ---------------------------------------------------------------------------
// Phase 3: tag logits + log_softmax. One warp per timestep.
// ---------------------------------------------------------------------------
__global__ __launch_bounds__(128) void tag_kernel(
    const float* __restrict__ Wt, const float* __restrict__ bt,
    float* __restrict__ out)
{
    int gw = (blockIdx.x * blockDim.x + threadIdx.x) >> 5;
    int lane = threadIdx.x & 31;
    if (gw >= TT) return;

    float4 h = *(const float4*)(g_h + gw * 4);

    float l0 = -1e30f, l1 = -1e30f;
    if (lane < NTAG) {
        const float* wr = Wt + lane * 4;
        l0 = bt[lane] + h.x * wr[0] + h.y * wr[1] + h.z * wr[2] + h.w * wr[3];
    }
    int tag2 = lane + 32;
    if (tag2 < NTAG) {
        const float* wr = Wt + tag2 * 4;
        l1 = bt[tag2] + h.x * wr[0] + h.y * wr[1] + h.z * wr[2] + h.w * wr[3];
    }

    float m = fmaxf(l0, l1);
#pragma unroll
    for (int off = 16; off > 0; off >>= 1)
        m = fmaxf(m, __shfl_xor_sync(0xffffffffu, m, off));

    float s = 0.0f;
    if (lane < NTAG) s += expf(l0 - m);
    if (tag2 < NTAG) s += expf(l1 - m);
#pragma unroll
    for (int off = 16; off > 0; off >>= 1)
        s += __shfl_xor_sync(0xffffffffu, s, off);

    float lz = m + logf(s);
    if (lane < NTAG) out[gw * NTAG + lane] = l0 - lz;
    if (tag2 < NTAG) out[gw * NTAG + tag2] = l1 - lz;
}

// ---------------------------------------------------------------------------
extern "C" void kernel_launch(void* const* d_in, const int* in_sizes, int n_in,
                              void* d_out, int out_size)
{
    const int*   sentence  = (const int*)d_in[0];
    const float* embedding = (const float*)d_in[1];
    const float* Wf  = (const float*)d_in[2];
    const float* bf  = (const float*)d_in[3];
    const float* Wi  = (const float*)d_in[4];
    const float* bi  = (const float*)d_in[5];
    const float* Wu  = (const float*)d_in[6];
    const float* bu  = (const float*)d_in[7];
    const float* Wo  = (const float*)d_in[8];
    const float* bo  = (const float*)d_in[9];
    const float* thf = (const float*)d_in[10];
    const float* thi = (const float*)d_in[11];
    const float* thu = (const float*)d_in[12];
    const float* tho = (const float*)d_in[13];
    const float* Wt  = (const float*)d_in[14];
    const float* bt  = (const float*)d_in[15];
    float* out = (float*)d_out;

    pre_kernel<<<512, 256>>>(sentence, embedding, Wf, bf, Wi, bi, Wu, bu,
                             Wo, bo, thf, thi, thu, tho);

    // Chunk-parallel scan: NPASS refinement passes, 256 chunks x 32 steps.
    scan_pass<false><<<NCHUNK, 32>>>(Wf, Wi, Wu, Wo, 0);
    scan_pass<false><<<NCHUNK, 32>>>(Wf, Wi, Wu, Wo, 1);
    scan_pass<false><<<NCHUNK, 32>>>(Wf, Wi, Wu, Wo, 2);
    scan_pass<true ><<<NCHUNK, 32>>>(Wf, Wi, Wu, Wo, 3);

    tag_kernel<<<TT / 4, 128>>>(Wt, bt, out);
}

// round 6
// speedup vs baseline: 58.1643x; 1.1593x over previous
#include <cuda_runtime.h>

#define TT 8192
#define EE 1024
#define DD 1028
#define NTAG 50

#define CHUNK 16
#define NCHUNK (TT / CHUNK)   // 512

// Scratch (no cudaMalloc allowed)
__device__ float g_pre[(TT + 1) * 16];      // pre-activations, +1 pad row for prefetch
__device__ float g_h[TT * 4];               // h outputs
__device__ float g_bnd[2][NCHUNK][8];       // chunk-boundary states: h0..3, c0..3

__device__ __forceinline__ float tanhf_fast(float x) {
    float y; asm("tanh.approx.f32 %0, %1;" : "=f"(y) : "f"(x)); return y;
}

// ---------------------------------------------------------------------------
// Phase 1: pre[t][g*4+w] = emb[sentence[t]] . W_g[w, :1024] + b_g[w] + th_g[w]
// One warp per timestep (max MLP). 8192 warps.
// ---------------------------------------------------------------------------
__global__ __launch_bounds__(256) void pre_kernel(
    const int* __restrict__ sentence, const float* __restrict__ emb,
    const float* __restrict__ Wf, const float* __restrict__ bf,
    const float* __restrict__ Wi, const float* __restrict__ bi,
    const float* __restrict__ Wu, const float* __restrict__ bu,
    const float* __restrict__ Wo, const float* __restrict__ bo,
    const float* __restrict__ thf, const float* __restrict__ thi,
    const float* __restrict__ thu, const float* __restrict__ tho)
{
    int t = (blockIdx.x * blockDim.x + threadIdx.x) >> 5;  // 0..8191
    int lane = threadIdx.x & 31;

    const float4* e4 = (const float4*)(emb + (size_t)sentence[t] * EE);
    const float* Wp[4] = {Wf, Wi, Wu, Wo};

    float acc[16];
#pragma unroll
    for (int k = 0; k < 16; k++) acc[k] = 0.0f;

    // 1024 floats = 256 float4; lane strides by 32 (8 iters)
    for (int j = lane; j < 256; j += 32) {
        float4 ev = e4[j];
#pragma unroll
        for (int k = 0; k < 16; k++) {
            float4 wv = ((const float4*)(Wp[k >> 2] + (k & 3) * DD))[j];
            acc[k] = fmaf(ev.x, wv.x, acc[k]);
            acc[k] = fmaf(ev.y, wv.y, acc[k]);
            acc[k] = fmaf(ev.z, wv.z, acc[k]);
            acc[k] = fmaf(ev.w, wv.w, acc[k]);
        }
    }

#pragma unroll
    for (int k = 0; k < 16; k++) {
#pragma unroll
        for (int off = 16; off > 0; off >>= 1)
            acc[k] += __shfl_xor_sync(0xffffffffu, acc[k], off);
    }

    if (lane == 0) {
        const float* bp[4] = {bf, bi, bu, bo};
        const float* tp[4] = {thf, thi, thu, tho};
        float4* dst = (float4*)(g_pre + t * 16);
#pragma unroll
        for (int g = 0; g < 4; g++) {
            float4 v;
            v.x = acc[g * 4 + 0] + bp[g][0] + tp[g][0];
            v.y = acc[g * 4 + 1] + bp[g][1] + tp[g][1];
            v.z = acc[g * 4 + 2] + bp[g][2] + tp[g][2];
            v.w = acc[g * 4 + 3] + bp[g][3] + tp[g][3];
            dst[g] = v;
        }
    }
}

// ---------------------------------------------------------------------------
// Phase 2: chunk-parallel LSTM scan with boundary refinement.
//
// Contraction: gate input q = prod(cos) in [-1,1] => f <= sigmoid(1)=0.731
// ALWAYS; realistic per-step contraction ~0.55-0.65. Pass 0: all 512 chunks
// (16 steps) from zero state. Pass k: chunk j restarts from pass k-1's end
// state of chunk j-1. 4 passes -> 48 refinement steps -> boundary error
// <= 0.83^48 ~ 1e-4 worst case, ~1e-9 realistic.
//
// lane = g*4+w (mirrored x2). qlayer collapses to parity cosine products:
// out0=c1c2c3, out1=c0c1, out2=c0c1c2, out3=c0c1c2c3.
// Activations via HW tanh: sigmoid(x) = 0.5*tanh(x/2)+0.5.
// ---------------------------------------------------------------------------
template<bool LAST>
__global__ __launch_bounds__(32) void scan_pass(
    const float* __restrict__ Wf, const float* __restrict__ Wi,
    const float* __restrict__ Wu, const float* __restrict__ Wo,
    int pass)
{
    __shared__ float4 s_pre[(CHUNK + 1) * 4];   // [t_local][gate] = wires w0..w3

    const unsigned FULL = 0xffffffffu;
    int j = blockIdx.x;            // chunk index
    int lane = threadIdx.x & 31;
    int w = lane & 3;
    int g = (lane >> 2) & 3;

    // Stage this chunk's pre rows (+1 prefetch row) into smem.
    const float4* gp4 = (const float4*)g_pre;
    for (int k = lane; k < (CHUNK + 1) * 4; k += 32)
        s_pre[k] = gp4[j * (CHUNK * 4) + k];

    const float* Wg = (g == 0) ? Wf : (g == 1) ? Wi : (g == 2) ? Wu : Wo;
    float wh[16];
#pragma unroll
    for (int jj = 0; jj < 16; jj++)
        wh[jj] = Wg[(jj >> 2) * DD + EE + (jj & 3)];

    // act = A2 * tanh(B2 * x) + C2 : sigmoid A2=C2=0.5,B2=0.5 ; tanh-gate A2=B2=1,C2=0
    float A2 = (g == 2) ? 1.0f : 0.5f;
    float B2 = (g == 2) ? 1.0f : 0.5f;
    float C2 = (g == 2) ? 0.0f : 0.5f;

    float h0 = 0.f, h1 = 0.f, h2 = 0.f, h3 = 0.f, cst = 0.f;
    if (pass > 0 && j > 0) {
        const float* b = g_bnd[(pass - 1) & 1][j - 1];
        h0 = b[0]; h1 = b[1]; h2 = b[2]; h3 = b[3];
        cst = b[4 + w];
    }

    __syncthreads();

    float4 pv = s_pre[g];
    float hn = 0.0f;
    float* ghp = g_h + j * CHUNK * 4 + (lane & 3);

    for (int tl = 0; tl < CHUNK; tl++) {
        float4 pn = s_pre[(tl + 1) * 4 + g];

        // Tree-form z: depth 3
        float z0 = fmaf(wh[1],  h1, fmaf(wh[0],  h0, pv.x)) + fmaf(wh[3],  h3, wh[2]  * h2);
        float z1 = fmaf(wh[5],  h1, fmaf(wh[4],  h0, pv.y)) + fmaf(wh[7],  h3, wh[6]  * h2);
        float z2 = fmaf(wh[9],  h1, fmaf(wh[8],  h0, pv.z)) + fmaf(wh[11], h3, wh[10] * h2);
        float z3 = fmaf(wh[13], h1, fmaf(wh[12], h0, pv.w)) + fmaf(wh[15], h3, wh[14] * h2);

        float c0 = __cosf(z0);
        float c1 = __cosf(z1);
        float c2 = __cosf(z2);
        float c3 = __cosf(z3);

        // Per-lane parity product x = u * v (q0=c1c2c3, q1=c0c1, q2=c0c1c2, q3=c0c1c2c3)
        float c12  = c1 * c2;
        float c23  = c2 * c3;
        float c123 = c1 * c23;
        float u = (w == 0) ? c1 : c0;
        float v = (w == 0) ? c23 : (w == 1) ? c1 : (w == 2) ? c12 : c123;
        float x = u * v;

        float act = fmaf(A2, tanhf_fast(B2 * x), C2);

        float fw = __shfl_sync(FULL, act,      w);
        float iw = __shfl_sync(FULL, act,  4 + w);
        float uw = __shfl_sync(FULL, act,  8 + w);
        float ow = __shfl_sync(FULL, act, 12 + w);

        cst = fmaf(fw, cst, iw * uw);
        hn = ow * tanhf_fast(cst);

        if (LAST) {
            if (lane < 4) ghp[tl * 4] = hn;
        }

        h0 = __shfl_sync(FULL, hn, 0);
        h1 = __shfl_sync(FULL, hn, 1);
        h2 = __shfl_sync(FULL, hn, 2);
        h3 = __shfl_sync(FULL, hn, 3);

        pv = pn;
    }

    if (!LAST && lane < 4) {
        g_bnd[pass & 1][j][lane]     = hn;   // wire `lane`'s h
        g_bnd[pass & 1][j][4 + lane] = cst;  // wire `lane`'s c
    }
}

// ---------------------------------------------------------------------------
// Phase 3: tag logits + log_softmax. One warp per timestep.
// ---------------------------------------------------------------------------
__global__ __launch_bounds__(128) void tag_kernel(
    const float* __restrict__ Wt, const float* __restrict__ bt,
    float* __restrict__ out)
{
    int gw = (blockIdx.x * blockDim.x + threadIdx.x) >> 5;
    int lane = threadIdx.x & 31;
    if (gw >= TT) return;

    float4 h = *(const float4*)(g_h + gw * 4);

    float l0 = -1e30f, l1 = -1e30f;
    if (lane < NTAG) {
        const float* wr = Wt + lane * 4;
        l0 = bt[lane] + h.x * wr[0] + h.y * wr[1] + h.z * wr[2] + h.w * wr[3];
    }
    int tag2 = lane + 32;
    if (tag2 < NTAG) {
        const float* wr = Wt + tag2 * 4;
        l1 = bt[tag2] + h.x * wr[0] + h.y * wr[1] + h.z * wr[2] + h.w * wr[3];
    }

    float m = fmaxf(l0, l1);
#pragma unroll
    for (int off = 16; off > 0; off >>= 1)
        m = fmaxf(m, __shfl_xor_sync(0xffffffffu, m, off));

    float s = 0.0f;
    if (lane < NTAG) s += expf(l0 - m);
    if (tag2 < NTAG) s += expf(l1 - m);
#pragma unroll
    for (int off = 16; off > 0; off >>= 1)
        s += __shfl_xor_sync(0xffffffffu, s, off);

    float lz = m + logf(s);
    if (lane < NTAG) out[gw * NTAG + lane] = l0 - lz;
    if (tag2 < NTAG) out[gw * NTAG + tag2] = l1 - lz;
}

// ---------------------------------------------------------------------------
extern "C" void kernel_launch(void* const* d_in, const int* in_sizes, int n_in,
                              void* d_out, int out_size)
{
    const int*   sentence  = (const int*)d_in[0];
    const float* embedding = (const float*)d_in[1];
    const float* Wf  = (const float*)d_in[2];
    const float* bf  = (const float*)d_in[3];
    const float* Wi  = (const float*)d_in[4];
    const float* bi  = (const float*)d_in[5];
    const float* Wu  = (const float*)d_in[6];
    const float* bu  = (const float*)d_in[7];
    const float* Wo  = (const float*)d_in[8];
    const float* bo  = (const float*)d_in[9];
    const float* thf = (const float*)d_in[10];
    const float* thi = (const float*)d_in[11];
    const float* thu = (const float*)d_in[12];
    const float* tho = (const float*)d_in[13];
    const float* Wt  = (const float*)d_in[14];
    const float* bt  = (const float*)d_in[15];
    float* out = (float*)d_out;

    // 8192 warps, 8 warps/block
    pre_kernel<<<1024, 256>>>(sentence, embedding, Wf, bf, Wi, bi, Wu, bu,
                              Wo, bo, thf, thi, thu, tho);

    // Chunk-parallel scan: 4 refinement passes, 512 chunks x 16 steps.
    scan_pass<false><<<NCHUNK, 32>>>(Wf, Wi, Wu, Wo, 0);
    scan_pass<false><<<NCHUNK, 32>>>(Wf, Wi, Wu, Wo, 1);
    scan_pass<false><<<NCHUNK, 32>>>(Wf, Wi, Wu, Wo, 2);
    scan_pass<true ><<<NCHUNK, 32>>>(Wf, Wi, Wu, Wo, 3);

    tag_kernel<<<TT / 4, 128>>>(Wt, bt, out);
}